// round 9
// baseline (speedup 1.0000x reference)
#include <cuda_runtime.h>
#include <cstdint>

#define N_NODES 100000
#define N_EDGES 1600000
#define D 128
#define K2 256

#define SCAN_NBLK ((N_NODES + 4095) / 4096)   // 25

// ---------------- scratch (device globals; no allocation allowed) ----------
__device__ int   g_deg[N_NODES];
__device__ int   g_off[N_NODES + 1];
__device__ int   g_cursor[N_NODES];
__device__ int   g_srcs[N_EDGES];
__device__ int   g_blksum[32];
__device__ int   g_blkoff[32];
__device__ float g_ahn[(size_t)N_NODES * D];   // normalized aggregated feats

// ---------------- small setup kernels ---------------------------------------
__global__ void k_zero_deg() {
    int i = blockIdx.x * blockDim.x + threadIdx.x;
    if (i < N_NODES) g_deg[i] = 0;
}

__global__ void k_count(const int* __restrict__ dst) {
    int e = blockIdx.x * blockDim.x + threadIdx.x;
    if (e < N_EDGES) atomicAdd(&g_deg[dst[e]], 1);
}

// ---- 3-kernel exclusive scan of g_deg -> g_off / g_cursor -------------------
__global__ void k_scan1() {
    __shared__ int wsum[32];
    const int b = blockIdx.x, t = threadIdx.x;
    const int lane = t & 31, wid = t >> 5;
    const int base = b * 4096 + t * 4;

    int v0 = 0, v1 = 0, v2 = 0, v3 = 0;
    if (base + 3 < N_NODES) {
        int4 vv = *(const int4*)&g_deg[base];
        v0 = vv.x; v1 = vv.y; v2 = vv.z; v3 = vv.w;
    } else {
        if (base + 0 < N_NODES) v0 = g_deg[base + 0];
        if (base + 1 < N_NODES) v1 = g_deg[base + 1];
        if (base + 2 < N_NODES) v2 = g_deg[base + 2];
        if (base + 3 < N_NODES) v3 = g_deg[base + 3];
    }
    int tsum = v0 + v1 + v2 + v3;

    int x = tsum;
#pragma unroll
    for (int o = 1; o < 32; o <<= 1) {
        int y = __shfl_up_sync(0xffffffffu, x, o);
        if (lane >= o) x += y;
    }
    if (lane == 31) wsum[wid] = x;
    __syncthreads();
    if (wid == 0) {
        int w = wsum[lane];
        int xx = w;
#pragma unroll
        for (int o = 1; o < 32; o <<= 1) {
            int y = __shfl_up_sync(0xffffffffu, xx, o);
            if (lane >= o) xx += y;
        }
        wsum[lane] = xx - w;
        if (lane == 31) g_blksum[b] = xx;
    }
    __syncthreads();

    int prefix = wsum[wid] + (x - tsum);
    if (base + 3 < N_NODES) {
        *(int4*)&g_off[base] = make_int4(prefix, prefix + v0,
                                         prefix + v0 + v1, prefix + v0 + v1 + v2);
    } else {
        if (base + 0 < N_NODES) g_off[base + 0] = prefix;
        if (base + 1 < N_NODES) g_off[base + 1] = prefix + v0;
        if (base + 2 < N_NODES) g_off[base + 2] = prefix + v0 + v1;
        if (base + 3 < N_NODES) g_off[base + 3] = prefix + v0 + v1 + v2;
    }
}

__global__ void k_scan2() {
    int t = threadIdx.x;   // 32 threads
    int v = (t < SCAN_NBLK) ? g_blksum[t] : 0;
    int x = v;
#pragma unroll
    for (int o = 1; o < 32; o <<= 1) {
        int y = __shfl_up_sync(0xffffffffu, x, o);
        if (t >= o) x += y;
    }
    if (t < SCAN_NBLK) g_blkoff[t] = x - v;
}

__global__ void k_scan3() {
    const int b = blockIdx.x, t = threadIdx.x;
    const int off = g_blkoff[b];
    const int base = b * 4096 + t * 4;
    if (base + 3 < N_NODES) {
        int4 vv = *(const int4*)&g_off[base];
        vv.x += off; vv.y += off; vv.z += off; vv.w += off;
        *(int4*)&g_off[base] = vv;
        *(int4*)&g_cursor[base] = vv;
    } else {
#pragma unroll
        for (int j = 0; j < 4; j++) {
            int idx = base + j;
            if (idx < N_NODES) {
                int val = g_off[idx] + off;
                g_off[idx] = val;
                g_cursor[idx] = val;
            }
        }
    }
    if (b == 0 && t == 0) g_off[N_NODES] = N_EDGES;
}

__global__ void k_scatter(const int* __restrict__ src, const int* __restrict__ dst) {
    int e = blockIdx.x * blockDim.x + threadIdx.x;
    if (e < N_EDGES) {
        int p = atomicAdd(&g_cursor[dst[e]], 1);
        g_srcs[p] = src[e];
    }
}

// ---------------- aggregation: one warp per dst node, 2 gathers in flight ----
__global__ void k_aggregate(const float* __restrict__ h) {
    int warp = (blockIdx.x * blockDim.x + threadIdx.x) >> 5;
    int lane = threadIdx.x & 31;
    if (warp >= N_NODES) return;
    int beg = g_off[warp];
    int end = g_off[warp + 1];
    const float4* h4 = (const float4*)h;
    float4 acc0 = make_float4(0.f, 0.f, 0.f, 0.f);
    float4 acc1 = make_float4(0.f, 0.f, 0.f, 0.f);
    int e = beg;
    for (; e + 1 < end; e += 2) {
        int s0 = __ldg(&g_srcs[e]);
        int s1 = __ldg(&g_srcs[e + 1]);
        float4 v0 = __ldg(&h4[(size_t)s0 * 32 + lane]);
        float4 v1 = __ldg(&h4[(size_t)s1 * 32 + lane]);
        acc0.x += v0.x; acc0.y += v0.y; acc0.z += v0.z; acc0.w += v0.w;
        acc1.x += v1.x; acc1.y += v1.y; acc1.z += v1.z; acc1.w += v1.w;
    }
    if (e < end) {
        int s0 = __ldg(&g_srcs[e]);
        float4 v0 = __ldg(&h4[(size_t)s0 * 32 + lane]);
        acc0.x += v0.x; acc0.y += v0.y; acc0.z += v0.z; acc0.w += v0.w;
    }
    acc0.x += acc1.x; acc0.y += acc1.y; acc0.z += acc1.z; acc0.w += acc1.w;
    float norm = (end > beg) ? 1.0f / (float)(end - beg) : 0.0f;
    acc0.x *= norm; acc0.y *= norm; acc0.z *= norm; acc0.w *= norm;
    ((float4*)g_ahn)[(size_t)warp * 32 + lane] = acc0;
}

// ------- merged GEMM: out = LN([h | ahn] @ W^T + b), ReLU --------------------
// Tile: 256 rows x 128 cols, 512 threads, 8x8 per thread, scalar FFMA inner.
// Full W (K=256) k-major in SMEM; A tiles (KT=32) double-buffered, source
// switches from h to g_ahn at kb=128.
#define MT 256
#define NT 128
#define KT 32
#define ASTRIDE (MT + 4)   // 260
#define ABUF (KT * ASTRIDE)
#define BSTRIDE (NT + 4)   // 132
#define GEMM_SMEM ((size_t)(2 * ABUF + K2 * BSTRIDE) * sizeof(float))

__global__ void __launch_bounds__(512, 1)
k_gemm_ln(const float* __restrict__ h,
          const float* __restrict__ W,
          const float* __restrict__ bias,
          const float* __restrict__ gamma,
          const float* __restrict__ beta,
          float* __restrict__ out)
{
    extern __shared__ float smem[];
    float* As = smem;                 // 2 x [KT][ASTRIDE]
    float* Bs = smem + 2 * ABUF;      // [K2][BSTRIDE]

    const int tid = threadIdx.x;
    const int tx = tid & 15;
    const int ty = tid >> 4;
    const int row0 = blockIdx.x * MT;

    // stage full W transposed: Bs[k][n] = W[n][k]
    {
        const float4* W4 = (const float4*)W;
#pragma unroll
        for (int q = 0; q < 16; q++) {
            int idx = tid + 512 * q;      // 0..8191
            int n = idx >> 6;             // 0..127
            int kc = idx & 63;            // float4 chunk over K=256
            float4 v = W4[(size_t)n * 64 + kc];
            int kk = kc * 4;
            Bs[(kk + 0) * BSTRIDE + n] = v.x;
            Bs[(kk + 1) * BSTRIDE + n] = v.y;
            Bs[(kk + 2) * BSTRIDE + n] = v.z;
            Bs[(kk + 3) * BSTRIDE + n] = v.w;
        }
    }

    float acc[8][8];
#pragma unroll
    for (int i = 0; i < 8; i++)
#pragma unroll
        for (int j = 0; j < 8; j++) acc[i][j] = 0.f;

    const float4* h4 = (const float4*)h;
    const float4* a4 = (const float4*)g_ahn;
    const int kc = tid & 7;
    const int mb = tid >> 3;

    // preload tile 0 (from h)
    float4 pre[4];
#pragma unroll
    for (int q = 0; q < 4; q++) {
        int row = row0 + mb + 64 * q;
        if (row >= N_NODES) row = N_NODES - 1;
        pre[q] = h4[(size_t)row * 32 + kc];
    }
    {
        int kk = kc * 4;
#pragma unroll
        for (int q = 0; q < 4; q++) {
            int m = mb + 64 * q;
            As[(kk + 0) * ASTRIDE + m] = pre[q].x;
            As[(kk + 1) * ASTRIDE + m] = pre[q].y;
            As[(kk + 2) * ASTRIDE + m] = pre[q].z;
            As[(kk + 3) * ASTRIDE + m] = pre[q].w;
        }
    }
    __syncthreads();

#pragma unroll
    for (int kb = 0; kb < K2; kb += KT) {
        const bool more = (kb + KT) < K2;
        if (more) {
            int kn = kb + KT;
            const float4* asrc = (kn < D) ? h4 : a4;
            int koff = ((kn < D) ? kn : (kn - D)) >> 2;
#pragma unroll
            for (int q = 0; q < 4; q++) {
                int row = row0 + mb + 64 * q;
                if (row >= N_NODES) row = N_NODES - 1;
                pre[q] = asrc[(size_t)row * 32 + koff + kc];
            }
        }

        const float* Acur = As + ((kb >> 5) & 1) * ABUF;

#pragma unroll 4
        for (int k = 0; k < KT; k++) {
            const float* brow = &Bs[(kb + k) * BSTRIDE + (tx << 3)];
            float4 b0 = *(const float4*)brow;
            float4 b1 = *(const float4*)(brow + 4);
            const float* arow = &Acur[k * ASTRIDE + (ty << 3)];
            float4 a0 = *(const float4*)arow;
            float4 a1 = *(const float4*)(arow + 4);
            float av[8] = {a0.x, a0.y, a0.z, a0.w, a1.x, a1.y, a1.z, a1.w};
            float bv[8] = {b0.x, b0.y, b0.z, b0.w, b1.x, b1.y, b1.z, b1.w};
#pragma unroll
            for (int i = 0; i < 8; i++)
#pragma unroll
                for (int j = 0; j < 8; j++)
                    acc[i][j] = fmaf(av[i], bv[j], acc[i][j]);
        }

        if (more) {
            float* Anxt = As + (((kb >> 5) + 1) & 1) * ABUF;
            int kk = kc * 4;
#pragma unroll
            for (int q = 0; q < 4; q++) {
                int m = mb + 64 * q;
                Anxt[(kk + 0) * ASTRIDE + m] = pre[q].x;
                Anxt[(kk + 1) * ASTRIDE + m] = pre[q].y;
                Anxt[(kk + 2) * ASTRIDE + m] = pre[q].z;
                Anxt[(kk + 3) * ASTRIDE + m] = pre[q].w;
            }
        }
        __syncthreads();
    }

    // epilogue: bias + LayerNorm + ReLU
    float gam[8], bet[8], bvec[8];
#pragma unroll
    for (int j = 0; j < 8; j++) {
        int c = tx * 8 + j;
        gam[j] = gamma[c];
        bet[j] = beta[c];
        bvec[j] = bias[c];
    }
#pragma unroll
    for (int i = 0; i < 8; i++) {
        float s = 0.f;
#pragma unroll
        for (int j = 0; j < 8; j++) {
            acc[i][j] += bvec[j];
            s += acc[i][j];
        }
#pragma unroll
        for (int o = 8; o >= 1; o >>= 1)
            s += __shfl_xor_sync(0xffffffffu, s, o);
        float mu = s * (1.0f / 128.0f);

        float vs = 0.f;
#pragma unroll
        for (int j = 0; j < 8; j++) {
            float dlt = acc[i][j] - mu;
            vs += dlt * dlt;
        }
#pragma unroll
        for (int o = 8; o >= 1; o >>= 1)
            vs += __shfl_xor_sync(0xffffffffu, vs, o);
        float inv = rsqrtf(vs * (1.0f / 128.0f) + 1e-5f);

        int row = row0 + ty * 8 + i;
        if (row < N_NODES) {
            float o8[8];
#pragma unroll
            for (int j = 0; j < 8; j++) {
                float v = (acc[i][j] - mu) * inv * gam[j] + bet[j];
                o8[j] = v > 0.f ? v : 0.f;
            }
            float4* dst4 = (float4*)&out[(size_t)row * 128 + tx * 8];
            dst4[0] = make_float4(o8[0], o8[1], o8[2], o8[3]);
            dst4[1] = make_float4(o8[4], o8[5], o8[6], o8[7]);
        }
    }
}

// ---------------- launcher ---------------------------------------------------
extern "C" void kernel_launch(void* const* d_in, const int* in_sizes, int n_in,
                              void* d_out, int out_size) {
    const float* h     = (const float*)d_in[0];
    const float* W     = (const float*)d_in[1];
    const float* b     = (const float*)d_in[2];
    const float* gamma = (const float*)d_in[3];
    const float* beta  = (const float*)d_in[4];
    const int*   src   = (const int*)d_in[5];
    const int*   dst   = (const int*)d_in[6];
    float* out = (float*)d_out;

    static int inited = 0;
    if (!inited) {
        cudaFuncSetAttribute(k_gemm_ln, cudaFuncAttributeMaxDynamicSharedMemorySize,
                             (int)GEMM_SMEM);
        inited = 1;
    }

    k_zero_deg<<<(N_NODES + 255) / 256, 256>>>();
    k_count<<<(N_EDGES + 255) / 256, 256>>>(dst);
    k_scan1<<<SCAN_NBLK, 1024>>>();
    k_scan2<<<1, 32>>>();
    k_scan3<<<SCAN_NBLK, 1024>>>();
    k_scatter<<<(N_EDGES + 255) / 256, 256>>>(src, dst);
    k_aggregate<<<(N_NODES * 32 + 255) / 256, 256>>>(h);

    const int GBLK = (N_NODES + MT - 1) / MT;
    k_gemm_ln<<<GBLK, 512, GEMM_SMEM>>>(h, W, b, gamma, beta, out);
}

// round 10
// speedup vs baseline: 1.2965x; 1.2965x over previous
#include <cuda_runtime.h>
#include <cuda_bf16.h>
#include <cstdint>

#define N_NODES 100000
#define N_EDGES 1600000
#define D 128
#define K2 256

#define SCAN_NBLK ((N_NODES + 4095) / 4096)   // 25

// ---------------- scratch (device globals; no allocation allowed) ----------
__device__ int   g_deg[N_NODES];
__device__ int   g_off[N_NODES + 1];
__device__ int   g_cursor[N_NODES];
__device__ int   g_srcs[N_EDGES];
__device__ int   g_blksum[32];
__device__ int   g_blkoff[32];
__device__ float g_ahn[(size_t)N_NODES * D];   // normalized aggregated feats

// ---------------- small setup kernels ---------------------------------------
__global__ void k_zero_deg() {
    int i = blockIdx.x * blockDim.x + threadIdx.x;
    if (i < N_NODES) g_deg[i] = 0;
}

__global__ void k_count(const int* __restrict__ dst) {
    int e = blockIdx.x * blockDim.x + threadIdx.x;
    if (e < N_EDGES) atomicAdd(&g_deg[dst[e]], 1);
}

// ---- 3-kernel exclusive scan of g_deg -> g_off / g_cursor -------------------
__global__ void k_scan1() {
    __shared__ int wsum[32];
    const int b = blockIdx.x, t = threadIdx.x;
    const int lane = t & 31, wid = t >> 5;
    const int base = b * 4096 + t * 4;

    int v0 = 0, v1 = 0, v2 = 0, v3 = 0;
    if (base + 3 < N_NODES) {
        int4 vv = *(const int4*)&g_deg[base];
        v0 = vv.x; v1 = vv.y; v2 = vv.z; v3 = vv.w;
    } else {
        if (base + 0 < N_NODES) v0 = g_deg[base + 0];
        if (base + 1 < N_NODES) v1 = g_deg[base + 1];
        if (base + 2 < N_NODES) v2 = g_deg[base + 2];
        if (base + 3 < N_NODES) v3 = g_deg[base + 3];
    }
    int tsum = v0 + v1 + v2 + v3;

    int x = tsum;
#pragma unroll
    for (int o = 1; o < 32; o <<= 1) {
        int y = __shfl_up_sync(0xffffffffu, x, o);
        if (lane >= o) x += y;
    }
    if (lane == 31) wsum[wid] = x;
    __syncthreads();
    if (wid == 0) {
        int w = wsum[lane];
        int xx = w;
#pragma unroll
        for (int o = 1; o < 32; o <<= 1) {
            int y = __shfl_up_sync(0xffffffffu, xx, o);
            if (lane >= o) xx += y;
        }
        wsum[lane] = xx - w;
        if (lane == 31) g_blksum[b] = xx;
    }
    __syncthreads();

    int prefix = wsum[wid] + (x - tsum);
    if (base + 3 < N_NODES) {
        *(int4*)&g_off[base] = make_int4(prefix, prefix + v0,
                                         prefix + v0 + v1, prefix + v0 + v1 + v2);
    } else {
        if (base + 0 < N_NODES) g_off[base + 0] = prefix;
        if (base + 1 < N_NODES) g_off[base + 1] = prefix + v0;
        if (base + 2 < N_NODES) g_off[base + 2] = prefix + v0 + v1;
        if (base + 3 < N_NODES) g_off[base + 3] = prefix + v0 + v1 + v2;
    }
}

__global__ void k_scan2() {
    int t = threadIdx.x;   // 32 threads
    int v = (t < SCAN_NBLK) ? g_blksum[t] : 0;
    int x = v;
#pragma unroll
    for (int o = 1; o < 32; o <<= 1) {
        int y = __shfl_up_sync(0xffffffffu, x, o);
        if (t >= o) x += y;
    }
    if (t < SCAN_NBLK) g_blkoff[t] = x - v;
}

__global__ void k_scan3() {
    const int b = blockIdx.x, t = threadIdx.x;
    const int off = g_blkoff[b];
    const int base = b * 4096 + t * 4;
    if (base + 3 < N_NODES) {
        int4 vv = *(const int4*)&g_off[base];
        vv.x += off; vv.y += off; vv.z += off; vv.w += off;
        *(int4*)&g_off[base] = vv;
        *(int4*)&g_cursor[base] = vv;
    } else {
#pragma unroll
        for (int j = 0; j < 4; j++) {
            int idx = base + j;
            if (idx < N_NODES) {
                int val = g_off[idx] + off;
                g_off[idx] = val;
                g_cursor[idx] = val;
            }
        }
    }
    if (b == 0 && t == 0) g_off[N_NODES] = N_EDGES;
}

__global__ void k_scatter(const int* __restrict__ src, const int* __restrict__ dst) {
    int e = blockIdx.x * blockDim.x + threadIdx.x;
    if (e < N_EDGES) {
        int p = atomicAdd(&g_cursor[dst[e]], 1);
        g_srcs[p] = src[e];
    }
}

// ---------------- aggregation: one warp per dst node, 2 gathers in flight ----
__global__ void k_aggregate(const float* __restrict__ h) {
    int warp = (blockIdx.x * blockDim.x + threadIdx.x) >> 5;
    int lane = threadIdx.x & 31;
    if (warp >= N_NODES) return;
    int beg = g_off[warp];
    int end = g_off[warp + 1];
    const float4* h4 = (const float4*)h;
    float4 acc0 = make_float4(0.f, 0.f, 0.f, 0.f);
    float4 acc1 = make_float4(0.f, 0.f, 0.f, 0.f);
    int e = beg;
    for (; e + 1 < end; e += 2) {
        int s0 = __ldg(&g_srcs[e]);
        int s1 = __ldg(&g_srcs[e + 1]);
        float4 v0 = __ldg(&h4[(size_t)s0 * 32 + lane]);
        float4 v1 = __ldg(&h4[(size_t)s1 * 32 + lane]);
        acc0.x += v0.x; acc0.y += v0.y; acc0.z += v0.z; acc0.w += v0.w;
        acc1.x += v1.x; acc1.y += v1.y; acc1.z += v1.z; acc1.w += v1.w;
    }
    if (e < end) {
        int s0 = __ldg(&g_srcs[e]);
        float4 v0 = __ldg(&h4[(size_t)s0 * 32 + lane]);
        acc0.x += v0.x; acc0.y += v0.y; acc0.z += v0.z; acc0.w += v0.w;
    }
    acc0.x += acc1.x; acc0.y += acc1.y; acc0.z += acc1.z; acc0.w += acc1.w;
    float norm = (end > beg) ? 1.0f / (float)(end - beg) : 0.0f;
    acc0.x *= norm; acc0.y *= norm; acc0.z *= norm; acc0.w *= norm;
    ((float4*)g_ahn)[(size_t)warp * 32 + lane] = acc0;
}

// =============== tensor-core GEMM + LN + ReLU (mma.sync bf16 hi/lo) ==========
// CTA: 128 rows x 128 cols, 512 threads (16 warps, 4x4 warp grid, 32x32/warp).
// K=256 in 4 chunks of 64. Per chunk: stage A (h|ahn) and W as bf16 hi+lo in
// SMEM (row stride 72 bf16 = conflict-free ldmatrix), 3-term mma accumulate.
// D = Ahi*Whi + Ahi*Wlo + Alo*Whi (fp32 accum; lo*lo dropped, ~2^-16 rel).
#define ASTR 72                      // bf16 elems per smem row (64 + 8 pad)
#define ABYTES (128 * ASTR * 2)      // 18432
#define OFF_WHI 0
#define OFF_WLO (ABYTES)
#define OFF_AHI (2 * ABYTES)
#define OFF_ALO (3 * ABYTES)
#define TC_SMEM (4 * ABYTES)         // 73728
#define OSTR 132                     // fp32 out staging row stride

__device__ __forceinline__ uint32_t smem_u32(const void* p) {
    uint32_t a;
    asm("{ .reg .u64 t; cvta.to.shared.u64 t, %1; cvt.u32.u64 %0, t; }"
        : "=r"(a) : "l"(p));
    return a;
}

__device__ __forceinline__ void ldm4(uint32_t* r, uint32_t addr) {
    asm volatile("ldmatrix.sync.aligned.m8n8.x4.shared.b16 {%0,%1,%2,%3}, [%4];"
        : "=r"(r[0]), "=r"(r[1]), "=r"(r[2]), "=r"(r[3]) : "r"(addr));
}

__device__ __forceinline__ void mma_bf16(float* c, const uint32_t* a,
                                         uint32_t b0, uint32_t b1) {
    asm volatile("mma.sync.aligned.m16n8k16.row.col.f32.bf16.bf16.f32 "
        "{%0,%1,%2,%3}, {%4,%5,%6,%7}, {%8,%9}, {%0,%1,%2,%3};"
        : "+f"(c[0]), "+f"(c[1]), "+f"(c[2]), "+f"(c[3])
        : "r"(a[0]), "r"(a[1]), "r"(a[2]), "r"(a[3]), "r"(b0), "r"(b1));
}

// split float4 -> 4 bf16 hi (2 uints) + 4 bf16 lo (2 uints)
__device__ __forceinline__ void split4(float4 v, uint32_t* hi, uint32_t* lo) {
    __nv_bfloat162 ha = __floats2bfloat162_rn(v.x, v.y);
    __nv_bfloat162 hb = __floats2bfloat162_rn(v.z, v.w);
    float2 fa = __bfloat1622float2(ha);
    float2 fb = __bfloat1622float2(hb);
    __nv_bfloat162 la = __floats2bfloat162_rn(v.x - fa.x, v.y - fa.y);
    __nv_bfloat162 lb = __floats2bfloat162_rn(v.z - fb.x, v.w - fb.y);
    hi[0] = *(uint32_t*)&ha; hi[1] = *(uint32_t*)&hb;
    lo[0] = *(uint32_t*)&la; lo[1] = *(uint32_t*)&lb;
}

__global__ void __launch_bounds__(512, 1)
k_gemm_tc(const float* __restrict__ h,
          const float* __restrict__ W,
          const float* __restrict__ bias,
          const float* __restrict__ gamma,
          const float* __restrict__ beta,
          float* __restrict__ out)
{
    extern __shared__ char sm[];
    const uint32_t smb = smem_u32(sm);

    const int tid = threadIdx.x;
    const int wid = tid >> 5;
    const int lane = tid & 31;
    const int wm = wid & 3;        // warp m tile (32 rows)
    const int wn = wid >> 2;       // warp n tile (32 cols)
    const int row0 = blockIdx.x * 128;

    // staging coords
    const int sr = tid >> 2;       // 0..127 (row / n)
    const int sq = tid & 3;        // 0..3 (k quarter: 16 elems)

    const float4* h4 = (const float4*)h;
    const float4* a4 = (const float4*)g_ahn;
    const float4* W4 = (const float4*)W;

    float c[2][4][4];
#pragma unroll
    for (int i = 0; i < 2; i++)
#pragma unroll
        for (int j = 0; j < 4; j++)
#pragma unroll
            for (int k = 0; k < 4; k++) c[i][j][k] = 0.f;

    // ldmatrix lane addressing (row = l&15, column half = l>>4)
    const int lrow = lane & 15;
    const int lhalfB = (lane >> 4) * 16;   // byte offset of 8-bf16 half
    const uint32_t aRowB = (uint32_t)(wm * 32 + lrow) * (ASTR * 2);
    const uint32_t wRowB = (uint32_t)(wn * 32 + lrow) * (ASTR * 2);

#pragma unroll 1
    for (int kb = 0; kb < 4; kb++) {
        __syncthreads();
        // ---- stage A chunk (h for kb<2, ahn for kb>=2) ----------------------
        {
            const float4* asrc = (kb < 2) ? h4 : a4;
            int koff = (kb & 1) * 16;
            int grow = row0 + sr;
            if (grow >= N_NODES) grow = N_NODES - 1;
            uint32_t hi[8], lo[8];
#pragma unroll
            for (int i = 0; i < 4; i++) {
                float4 v = __ldg(&asrc[(size_t)grow * 32 + koff + sq * 4 + i]);
                split4(v, &hi[2 * i], &lo[2 * i]);
            }
            char* pa = sm + OFF_AHI + (sr * ASTR + sq * 16) * 2;
            char* pl = sm + OFF_ALO + (sr * ASTR + sq * 16) * 2;
            *(uint4*)pa = make_uint4(hi[0], hi[1], hi[2], hi[3]);
            *(uint4*)(pa + 16) = make_uint4(hi[4], hi[5], hi[6], hi[7]);
            *(uint4*)pl = make_uint4(lo[0], lo[1], lo[2], lo[3]);
            *(uint4*)(pl + 16) = make_uint4(lo[4], lo[5], lo[6], lo[7]);
        }
        // ---- stage W chunk ---------------------------------------------------
        {
            uint32_t hi[8], lo[8];
#pragma unroll
            for (int i = 0; i < 4; i++) {
                float4 v = __ldg(&W4[(size_t)sr * 64 + kb * 16 + sq * 4 + i]);
                split4(v, &hi[2 * i], &lo[2 * i]);
            }
            char* pa = sm + OFF_WHI + (sr * ASTR + sq * 16) * 2;
            char* pl = sm + OFF_WLO + (sr * ASTR + sq * 16) * 2;
            *(uint4*)pa = make_uint4(hi[0], hi[1], hi[2], hi[3]);
            *(uint4*)(pa + 16) = make_uint4(hi[4], hi[5], hi[6], hi[7]);
            *(uint4*)pl = make_uint4(lo[0], lo[1], lo[2], lo[3]);
            *(uint4*)(pl + 16) = make_uint4(lo[4], lo[5], lo[6], lo[7]);
        }
        __syncthreads();

        // ---- mma over this chunk: 4 k-steps of 16 ---------------------------
#pragma unroll
        for (int ks = 0; ks < 4; ks++) {
            const uint32_t cb = (uint32_t)(ks * 32 + lhalfB);   // byte col offset
            uint32_t ah[2][4], al[2][4], wh[2][4], wl[2][4];
#pragma unroll
            for (int mf = 0; mf < 2; mf++) {
                uint32_t ro = aRowB + mf * 16 * (ASTR * 2) + cb;
                ldm4(ah[mf], smb + OFF_AHI + ro);
                ldm4(al[mf], smb + OFF_ALO + ro);
            }
#pragma unroll
            for (int nx = 0; nx < 2; nx++) {
                uint32_t ro = wRowB + nx * 16 * (ASTR * 2) + cb;
                ldm4(wh[nx], smb + OFF_WHI + ro);
                ldm4(wl[nx], smb + OFF_WLO + ro);
            }
#pragma unroll
            for (int mf = 0; mf < 2; mf++)
#pragma unroll
                for (int nx = 0; nx < 2; nx++)
#pragma unroll
                    for (int sub = 0; sub < 2; sub++) {
                        int n8 = nx * 2 + sub;
                        mma_bf16(c[mf][n8], ah[mf], wh[nx][sub], wh[nx][sub + 2]);
                        mma_bf16(c[mf][n8], ah[mf], wl[nx][sub], wl[nx][sub + 2]);
                        mma_bf16(c[mf][n8], al[mf], wh[nx][sub], wh[nx][sub + 2]);
                    }
        }
    }

    // ---- stage C frags to SMEM (padded stride, conflict-free) ---------------
    __syncthreads();
    float* outS = (float*)sm;
#pragma unroll
    for (int mf = 0; mf < 2; mf++)
#pragma unroll
        for (int n8 = 0; n8 < 4; n8++) {
            int rr = wm * 32 + mf * 16 + (lane >> 2);
            int cc = wn * 32 + n8 * 8 + (lane & 3) * 2;
            *(float2*)&outS[rr * OSTR + cc] =
                make_float2(c[mf][n8][0], c[mf][n8][1]);
            *(float2*)&outS[(rr + 8) * OSTR + cc] =
                make_float2(c[mf][n8][2], c[mf][n8][3]);
        }
    __syncthreads();

    // ---- bias + LayerNorm + ReLU; 4 threads per row ------------------------
    {
        int r = tid >> 2;
        int q = tid & 3;
        float vals[32];
        float s = 0.f, ss = 0.f;
#pragma unroll
        for (int j = 0; j < 8; j++) {
            int col = q * 32 + j * 4;
            float4 y = *(const float4*)&outS[r * OSTR + col];
            float4 bb = __ldg((const float4*)&bias[col]);
            y.x += bb.x; y.y += bb.y; y.z += bb.z; y.w += bb.w;
            vals[4 * j + 0] = y.x; vals[4 * j + 1] = y.y;
            vals[4 * j + 2] = y.z; vals[4 * j + 3] = y.w;
            s += y.x + y.y + y.z + y.w;
            ss += y.x * y.x + y.y * y.y + y.z * y.z + y.w * y.w;
        }
        s  += __shfl_xor_sync(0xffffffffu, s, 1);
        s  += __shfl_xor_sync(0xffffffffu, s, 2);
        ss += __shfl_xor_sync(0xffffffffu, ss, 1);
        ss += __shfl_xor_sync(0xffffffffu, ss, 2);
        float mu = s * (1.0f / 128.0f);
        float var = ss * (1.0f / 128.0f) - mu * mu;
        float inv = rsqrtf(var + 1e-5f);

        int grow = row0 + r;
        if (grow < N_NODES) {
            float* gout = &out[(size_t)grow * 128];
#pragma unroll
            for (int j = 0; j < 8; j++) {
                int col = q * 32 + j * 4;
                float4 gm = __ldg((const float4*)&gamma[col]);
                float4 bt = __ldg((const float4*)&beta[col]);
                float4 o;
                o.x = (vals[4 * j + 0] - mu) * inv * gm.x + bt.x;
                o.y = (vals[4 * j + 1] - mu) * inv * gm.y + bt.y;
                o.z = (vals[4 * j + 2] - mu) * inv * gm.z + bt.z;
                o.w = (vals[4 * j + 3] - mu) * inv * gm.w + bt.w;
                o.x = o.x > 0.f ? o.x : 0.f;
                o.y = o.y > 0.f ? o.y : 0.f;
                o.z = o.z > 0.f ? o.z : 0.f;
                o.w = o.w > 0.f ? o.w : 0.f;
                *(float4*)&gout[col] = o;
            }
        }
    }
}

// ---------------- launcher ---------------------------------------------------
extern "C" void kernel_launch(void* const* d_in, const int* in_sizes, int n_in,
                              void* d_out, int out_size) {
    const float* h     = (const float*)d_in[0];
    const float* W     = (const float*)d_in[1];
    const float* b     = (const float*)d_in[2];
    const float* gamma = (const float*)d_in[3];
    const float* beta  = (const float*)d_in[4];
    const int*   src   = (const int*)d_in[5];
    const int*   dst   = (const int*)d_in[6];
    float* out = (float*)d_out;

    static int inited = 0;
    if (!inited) {
        cudaFuncSetAttribute(k_gemm_tc, cudaFuncAttributeMaxDynamicSharedMemorySize,
                             TC_SMEM);
        inited = 1;
    }

    k_zero_deg<<<(N_NODES + 255) / 256, 256>>>();
    k_count<<<(N_EDGES + 255) / 256, 256>>>(dst);
    k_scan1<<<SCAN_NBLK, 1024>>>();
    k_scan2<<<1, 32>>>();
    k_scan3<<<SCAN_NBLK, 1024>>>();
    k_scatter<<<(N_EDGES + 255) / 256, 256>>>(src, dst);
    k_aggregate<<<(N_NODES * 32 + 255) / 256, 256>>>(h);

    const int GBLK = (N_NODES + 127) / 128;   // 782
    k_gemm_tc<<<GBLK, 512, TC_SMEM>>>(h, W, b, gamma, beta, out);
}

// round 11
// speedup vs baseline: 1.3836x; 1.0672x over previous
#include <cuda_runtime.h>
#include <cuda_bf16.h>
#include <cstdint>

#define N_NODES 100000
#define N_EDGES 1600000
#define D 128
#define K2 256

#define SCAN_NBLK ((N_NODES + 4095) / 4096)   // 25

// ---------------- scratch (device globals; no allocation allowed) ----------
__device__ int   g_deg[N_NODES];
__device__ int   g_off[N_NODES + 1];
__device__ int   g_cursor[N_NODES];
__device__ int   g_srcs[N_EDGES];
__device__ int   g_blksum[32];
__device__ int   g_blkoff[32];
__device__ float g_ahn[(size_t)N_NODES * D];        // aggregated feats
__device__ __nv_bfloat16 g_Whi[128 * 256];          // W bf16 hi
__device__ __nv_bfloat16 g_Wlo[128 * 256];          // W bf16 lo

// ---------------- small setup kernels ---------------------------------------
__global__ void k_zero_deg() {
    int i = blockIdx.x * blockDim.x + threadIdx.x;
    if (i < N_NODES) g_deg[i] = 0;
}

__global__ void k_count(const int* __restrict__ dst) {
    int e = blockIdx.x * blockDim.x + threadIdx.x;
    if (e < N_EDGES) atomicAdd(&g_deg[dst[e]], 1);
}

__global__ void k_convW(const float* __restrict__ W) {
    int i = blockIdx.x * blockDim.x + threadIdx.x;   // 0..32767
    float v = W[i];
    __nv_bfloat16 hi = __float2bfloat16(v);
    g_Whi[i] = hi;
    g_Wlo[i] = __float2bfloat16(v - __bfloat162float(hi));
}

// ---- 3-kernel exclusive scan of g_deg -> g_off / g_cursor -------------------
__global__ void k_scan1() {
    __shared__ int wsum[32];
    const int b = blockIdx.x, t = threadIdx.x;
    const int lane = t & 31, wid = t >> 5;
    const int base = b * 4096 + t * 4;

    int v0 = 0, v1 = 0, v2 = 0, v3 = 0;
    if (base + 3 < N_NODES) {
        int4 vv = *(const int4*)&g_deg[base];
        v0 = vv.x; v1 = vv.y; v2 = vv.z; v3 = vv.w;
    } else {
        if (base + 0 < N_NODES) v0 = g_deg[base + 0];
        if (base + 1 < N_NODES) v1 = g_deg[base + 1];
        if (base + 2 < N_NODES) v2 = g_deg[base + 2];
        if (base + 3 < N_NODES) v3 = g_deg[base + 3];
    }
    int tsum = v0 + v1 + v2 + v3;

    int x = tsum;
#pragma unroll
    for (int o = 1; o < 32; o <<= 1) {
        int y = __shfl_up_sync(0xffffffffu, x, o);
        if (lane >= o) x += y;
    }
    if (lane == 31) wsum[wid] = x;
    __syncthreads();
    if (wid == 0) {
        int w = wsum[lane];
        int xx = w;
#pragma unroll
        for (int o = 1; o < 32; o <<= 1) {
            int y = __shfl_up_sync(0xffffffffu, xx, o);
            if (lane >= o) xx += y;
        }
        wsum[lane] = xx - w;
        if (lane == 31) g_blksum[b] = xx;
    }
    __syncthreads();

    int prefix = wsum[wid] + (x - tsum);
    if (base + 3 < N_NODES) {
        *(int4*)&g_off[base] = make_int4(prefix, prefix + v0,
                                         prefix + v0 + v1, prefix + v0 + v1 + v2);
    } else {
        if (base + 0 < N_NODES) g_off[base + 0] = prefix;
        if (base + 1 < N_NODES) g_off[base + 1] = prefix + v0;
        if (base + 2 < N_NODES) g_off[base + 2] = prefix + v0 + v1;
        if (base + 3 < N_NODES) g_off[base + 3] = prefix + v0 + v1 + v2;
    }
}

__global__ void k_scan2() {
    int t = threadIdx.x;   // 32 threads
    int v = (t < SCAN_NBLK) ? g_blksum[t] : 0;
    int x = v;
#pragma unroll
    for (int o = 1; o < 32; o <<= 1) {
        int y = __shfl_up_sync(0xffffffffu, x, o);
        if (t >= o) x += y;
    }
    if (t < SCAN_NBLK) g_blkoff[t] = x - v;
}

__global__ void k_scan3() {
    const int b = blockIdx.x, t = threadIdx.x;
    const int off = g_blkoff[b];
    const int base = b * 4096 + t * 4;
    if (base + 3 < N_NODES) {
        int4 vv = *(const int4*)&g_off[base];
        vv.x += off; vv.y += off; vv.z += off; vv.w += off;
        *(int4*)&g_off[base] = vv;
        *(int4*)&g_cursor[base] = vv;
    } else {
#pragma unroll
        for (int j = 0; j < 4; j++) {
            int idx = base + j;
            if (idx < N_NODES) {
                int val = g_off[idx] + off;
                g_off[idx] = val;
                g_cursor[idx] = val;
            }
        }
    }
    if (b == 0 && t == 0) g_off[N_NODES] = N_EDGES;
}

__global__ void k_scatter(const int* __restrict__ src, const int* __restrict__ dst) {
    int e = blockIdx.x * blockDim.x + threadIdx.x;
    if (e < N_EDGES) {
        int p = atomicAdd(&g_cursor[dst[e]], 1);
        g_srcs[p] = src[e];
    }
}

// ---------------- aggregation: one warp per dst node, 2 gathers in flight ----
__global__ void k_aggregate(const float* __restrict__ h) {
    int warp = (blockIdx.x * blockDim.x + threadIdx.x) >> 5;
    int lane = threadIdx.x & 31;
    if (warp >= N_NODES) return;
    int beg = g_off[warp];
    int end = g_off[warp + 1];
    const float4* h4 = (const float4*)h;
    float4 acc0 = make_float4(0.f, 0.f, 0.f, 0.f);
    float4 acc1 = make_float4(0.f, 0.f, 0.f, 0.f);
    int e = beg;
    for (; e + 1 < end; e += 2) {
        int s0 = __ldg(&g_srcs[e]);
        int s1 = __ldg(&g_srcs[e + 1]);
        float4 v0 = __ldg(&h4[(size_t)s0 * 32 + lane]);
        float4 v1 = __ldg(&h4[(size_t)s1 * 32 + lane]);
        acc0.x += v0.x; acc0.y += v0.y; acc0.z += v0.z; acc0.w += v0.w;
        acc1.x += v1.x; acc1.y += v1.y; acc1.z += v1.z; acc1.w += v1.w;
    }
    if (e < end) {
        int s0 = __ldg(&g_srcs[e]);
        float4 v0 = __ldg(&h4[(size_t)s0 * 32 + lane]);
        acc0.x += v0.x; acc0.y += v0.y; acc0.z += v0.z; acc0.w += v0.w;
    }
    acc0.x += acc1.x; acc0.y += acc1.y; acc0.z += acc1.z; acc0.w += acc1.w;
    float norm = (end > beg) ? 1.0f / (float)(end - beg) : 0.0f;
    acc0.x *= norm; acc0.y *= norm; acc0.z *= norm; acc0.w *= norm;
    ((float4*)g_ahn)[(size_t)warp * 32 + lane] = acc0;
}

// =============== tensor-core GEMM + LN + ReLU (mma.sync bf16 hi/lo) ==========
// CTA: 128 rows x 128 cols, 512 threads (16 warps, 4x4 grid, 32x32 per warp).
// K=256 in 4 chunks of 64, DOUBLE-BUFFERED: next chunk's global loads issue
// before the current chunk's 48 MMAs; convert/store after. W pre-converted.
#define ASTR 72                        // bf16 per smem row (64 + 8 pad)
#define ABYTES (128 * ASTR * 2)        // 18432
#define BUFBYTES (4 * ABYTES)          // 73728: WHI|WLO|AHI|ALO
#define OFF_WHI 0
#define OFF_WLO (ABYTES)
#define OFF_AHI (2 * ABYTES)
#define OFF_ALO (3 * ABYTES)
#define TC_SMEM (2 * BUFBYTES)         // 147456
#define OSTR 132                       // fp32 out staging row stride

__device__ __forceinline__ uint32_t smem_u32(const void* p) {
    uint32_t a;
    asm("{ .reg .u64 t; cvta.to.shared.u64 t, %1; cvt.u32.u64 %0, t; }"
        : "=r"(a) : "l"(p));
    return a;
}

__device__ __forceinline__ void ldm4(uint32_t* r, uint32_t addr) {
    asm volatile("ldmatrix.sync.aligned.m8n8.x4.shared.b16 {%0,%1,%2,%3}, [%4];"
        : "=r"(r[0]), "=r"(r[1]), "=r"(r[2]), "=r"(r[3]) : "r"(addr));
}

__device__ __forceinline__ void mma_bf16(float* c, const uint32_t* a,
                                         uint32_t b0, uint32_t b1) {
    asm volatile("mma.sync.aligned.m16n8k16.row.col.f32.bf16.bf16.f32 "
        "{%0,%1,%2,%3}, {%4,%5,%6,%7}, {%8,%9}, {%0,%1,%2,%3};"
        : "+f"(c[0]), "+f"(c[1]), "+f"(c[2]), "+f"(c[3])
        : "r"(a[0]), "r"(a[1]), "r"(a[2]), "r"(a[3]), "r"(b0), "r"(b1));
}

__device__ __forceinline__ void split4(float4 v, uint32_t* hi, uint32_t* lo) {
    __nv_bfloat162 ha = __floats2bfloat162_rn(v.x, v.y);
    __nv_bfloat162 hb = __floats2bfloat162_rn(v.z, v.w);
    float2 fa = __bfloat1622float2(ha);
    float2 fb = __bfloat1622float2(hb);
    __nv_bfloat162 la = __floats2bfloat162_rn(v.x - fa.x, v.y - fa.y);
    __nv_bfloat162 lb = __floats2bfloat162_rn(v.z - fb.x, v.w - fb.y);
    hi[0] = *(uint32_t*)&ha; hi[1] = *(uint32_t*)&hb;
    lo[0] = *(uint32_t*)&la; lo[1] = *(uint32_t*)&lb;
}

__global__ void __launch_bounds__(512, 1)
k_gemm_tc(const float* __restrict__ h,
          const float* __restrict__ bias,
          const float* __restrict__ gamma,
          const float* __restrict__ beta,
          float* __restrict__ out)
{
    extern __shared__ char sm[];
    const uint32_t smb = smem_u32(sm);

    const int tid = threadIdx.x;
    const int wid = tid >> 5;
    const int lane = tid & 31;
    const int wm = wid & 3;
    const int wn = wid >> 2;
    const int row0 = blockIdx.x * 128;

    const int sr = tid >> 2;       // staging row 0..127
    const int sq = tid & 3;        // staging k-quarter (16 bf16)

    const float4* h4 = (const float4*)h;
    const float4* a4 = (const float4*)g_ahn;

    float c[2][4][4];
#pragma unroll
    for (int i = 0; i < 2; i++)
#pragma unroll
        for (int j = 0; j < 4; j++)
#pragma unroll
            for (int k = 0; k < 4; k++) c[i][j][k] = 0.f;

    const int lrow = lane & 15;
    const int lhalfB = (lane >> 4) * 16;
    const uint32_t aRowB = (uint32_t)(wm * 32 + lrow) * (ASTR * 2);
    const uint32_t wRowB = (uint32_t)(wn * 32 + lrow) * (ASTR * 2);

    int growA = row0 + sr;
    if (growA >= N_NODES) growA = N_NODES - 1;
    const size_t aBase = (size_t)growA * 32;
    const int wIdx = sr * 256 + sq * 16;   // bf16 index into g_W{hi,lo}
    const uint32_t stByteOff = (uint32_t)((sr * ASTR + sq * 16) * 2);

    // ---- stage chunk 0 into buffer 0 ----------------------------------------
    {
        uint32_t hi[8], lo[8];
#pragma unroll
        for (int i = 0; i < 4; i++) {
            float4 v = __ldg(&h4[aBase + sq * 4 + i]);
            split4(v, &hi[2 * i], &lo[2 * i]);
        }
        char* pa = sm + OFF_AHI + stByteOff;
        char* pl = sm + OFF_ALO + stByteOff;
        *(uint4*)pa = make_uint4(hi[0], hi[1], hi[2], hi[3]);
        *(uint4*)(pa + 16) = make_uint4(hi[4], hi[5], hi[6], hi[7]);
        *(uint4*)pl = make_uint4(lo[0], lo[1], lo[2], lo[3]);
        *(uint4*)(pl + 16) = make_uint4(lo[4], lo[5], lo[6], lo[7]);

        uint4 wh0 = __ldg((const uint4*)&g_Whi[wIdx]);
        uint4 wh1 = __ldg((const uint4*)&g_Whi[wIdx + 8]);
        uint4 wl0 = __ldg((const uint4*)&g_Wlo[wIdx]);
        uint4 wl1 = __ldg((const uint4*)&g_Wlo[wIdx + 8]);
        char* pw = sm + OFF_WHI + stByteOff;
        char* pv = sm + OFF_WLO + stByteOff;
        *(uint4*)pw = wh0; *(uint4*)(pw + 16) = wh1;
        *(uint4*)pv = wl0; *(uint4*)(pv + 16) = wl1;
    }
    __syncthreads();

#pragma unroll
    for (int kb = 0; kb < 4; kb++) {
        const bool more = kb < 3;
        float4 preA[4];
        uint4 preW[4];
        if (more) {
            int kn = kb + 1;
            const float4* asrc = (kn < 2) ? h4 : a4;
            int koff = (kn & 1) * 16;
#pragma unroll
            for (int i = 0; i < 4; i++)
                preA[i] = __ldg(&asrc[aBase + koff + sq * 4 + i]);
            preW[0] = __ldg((const uint4*)&g_Whi[wIdx + kn * 64]);
            preW[1] = __ldg((const uint4*)&g_Whi[wIdx + kn * 64 + 8]);
            preW[2] = __ldg((const uint4*)&g_Wlo[wIdx + kn * 64]);
            preW[3] = __ldg((const uint4*)&g_Wlo[wIdx + kn * 64 + 8]);
        }

        const uint32_t bufB = (uint32_t)((kb & 1) * BUFBYTES);
        // ---- mma over current chunk: 4 k-steps of 16 ------------------------
#pragma unroll
        for (int ks = 0; ks < 4; ks++) {
            const uint32_t cb = (uint32_t)(ks * 32 + lhalfB);
            uint32_t ah[2][4], al[2][4], wh[2][4], wl[2][4];
#pragma unroll
            for (int mf = 0; mf < 2; mf++) {
                uint32_t ro = aRowB + mf * 16 * (ASTR * 2) + cb;
                ldm4(ah[mf], smb + bufB + OFF_AHI + ro);
                ldm4(al[mf], smb + bufB + OFF_ALO + ro);
            }
#pragma unroll
            for (int nx = 0; nx < 2; nx++) {
                uint32_t ro = wRowB + nx * 16 * (ASTR * 2) + cb;
                ldm4(wh[nx], smb + bufB + OFF_WHI + ro);
                ldm4(wl[nx], smb + bufB + OFF_WLO + ro);
            }
#pragma unroll
            for (int mf = 0; mf < 2; mf++)
#pragma unroll
                for (int nx = 0; nx < 2; nx++)
#pragma unroll
                    for (int sub = 0; sub < 2; sub++) {
                        int n8 = nx * 2 + sub;
                        mma_bf16(c[mf][n8], ah[mf], wh[nx][sub], wh[nx][sub + 2]);
                        mma_bf16(c[mf][n8], ah[mf], wl[nx][sub], wl[nx][sub + 2]);
                        mma_bf16(c[mf][n8], al[mf], wh[nx][sub], wh[nx][sub + 2]);
                    }
        }

        if (more) {
            const uint32_t nbB = (uint32_t)(((kb + 1) & 1) * BUFBYTES);
            uint32_t hi[8], lo[8];
#pragma unroll
            for (int i = 0; i < 4; i++)
                split4(preA[i], &hi[2 * i], &lo[2 * i]);
            char* pa = sm + nbB + OFF_AHI + stByteOff;
            char* pl = sm + nbB + OFF_ALO + stByteOff;
            *(uint4*)pa = make_uint4(hi[0], hi[1], hi[2], hi[3]);
            *(uint4*)(pa + 16) = make_uint4(hi[4], hi[5], hi[6], hi[7]);
            *(uint4*)pl = make_uint4(lo[0], lo[1], lo[2], lo[3]);
            *(uint4*)(pl + 16) = make_uint4(lo[4], lo[5], lo[6], lo[7]);
            char* pw = sm + nbB + OFF_WHI + stByteOff;
            char* pv = sm + nbB + OFF_WLO + stByteOff;
            *(uint4*)pw = preW[0]; *(uint4*)(pw + 16) = preW[1];
            *(uint4*)pv = preW[2]; *(uint4*)(pv + 16) = preW[3];
            __syncthreads();
        }
    }

    // ---- stage C frags to SMEM (padded stride) -------------------------------
    __syncthreads();
    float* outS = (float*)sm;
#pragma unroll
    for (int mf = 0; mf < 2; mf++)
#pragma unroll
        for (int n8 = 0; n8 < 4; n8++) {
            int rr = wm * 32 + mf * 16 + (lane >> 2);
            int cc = wn * 32 + n8 * 8 + (lane & 3) * 2;
            *(float2*)&outS[rr * OSTR + cc] =
                make_float2(c[mf][n8][0], c[mf][n8][1]);
            *(float2*)&outS[(rr + 8) * OSTR + cc] =
                make_float2(c[mf][n8][2], c[mf][n8][3]);
        }
    __syncthreads();

    // ---- bias + LayerNorm + ReLU; 4 threads per row --------------------------
    {
        int r = tid >> 2;
        int q = tid & 3;
        float vals[32];
        float s = 0.f, ss = 0.f;
#pragma unroll
        for (int j = 0; j < 8; j++) {
            int col = q * 32 + j * 4;
            float4 y = *(const float4*)&outS[r * OSTR + col];
            float4 bb = __ldg((const float4*)&bias[col]);
            y.x += bb.x; y.y += bb.y; y.z += bb.z; y.w += bb.w;
            vals[4 * j + 0] = y.x; vals[4 * j + 1] = y.y;
            vals[4 * j + 2] = y.z; vals[4 * j + 3] = y.w;
            s += y.x + y.y + y.z + y.w;
            ss += y.x * y.x + y.y * y.y + y.z * y.z + y.w * y.w;
        }
        s  += __shfl_xor_sync(0xffffffffu, s, 1);
        s  += __shfl_xor_sync(0xffffffffu, s, 2);
        ss += __shfl_xor_sync(0xffffffffu, ss, 1);
        ss += __shfl_xor_sync(0xffffffffu, ss, 2);
        float mu = s * (1.0f / 128.0f);
        float var = ss * (1.0f / 128.0f) - mu * mu;
        float inv = rsqrtf(var + 1e-5f);

        int grow = row0 + r;
        if (grow < N_NODES) {
            float* gout = &out[(size_t)grow * 128];
#pragma unroll
            for (int j = 0; j < 8; j++) {
                int col = q * 32 + j * 4;
                float4 gm = __ldg((const float4*)&gamma[col]);
                float4 bt = __ldg((const float4*)&beta[col]);
                float4 o;
                o.x = (vals[4 * j + 0] - mu) * inv * gm.x + bt.x;
                o.y = (vals[4 * j + 1] - mu) * inv * gm.y + bt.y;
                o.z = (vals[4 * j + 2] - mu) * inv * gm.z + bt.z;
                o.w = (vals[4 * j + 3] - mu) * inv * gm.w + bt.w;
                o.x = o.x > 0.f ? o.x : 0.f;
                o.y = o.y > 0.f ? o.y : 0.f;
                o.z = o.z > 0.f ? o.z : 0.f;
                o.w = o.w > 0.f ? o.w : 0.f;
                *(float4*)&gout[col] = o;
            }
        }
    }
}

// ---------------- launcher ---------------------------------------------------
extern "C" void kernel_launch(void* const* d_in, const int* in_sizes, int n_in,
                              void* d_out, int out_size) {
    const float* h     = (const float*)d_in[0];
    const float* W     = (const float*)d_in[1];
    const float* b     = (const float*)d_in[2];
    const float* gamma = (const float*)d_in[3];
    const float* beta  = (const float*)d_in[4];
    const int*   src   = (const int*)d_in[5];
    const int*   dst   = (const int*)d_in[6];
    float* out = (float*)d_out;

    static int inited = 0;
    if (!inited) {
        cudaFuncSetAttribute(k_gemm_tc, cudaFuncAttributeMaxDynamicSharedMemorySize,
                             TC_SMEM);
        inited = 1;
    }

    k_convW<<<128, 256>>>(W);
    k_zero_deg<<<(N_NODES + 255) / 256, 256>>>();
    k_count<<<(N_EDGES + 255) / 256, 256>>>(dst);
    k_scan1<<<SCAN_NBLK, 1024>>>();
    k_scan2<<<1, 32>>>();
    k_scan3<<<SCAN_NBLK, 1024>>>();
    k_scatter<<<(N_EDGES + 255) / 256, 256>>>(src, dst);
    k_aggregate<<<(N_NODES * 32 + 255) / 256, 256>>>(h);

    const int GBLK = (N_NODES + 127) / 128;   // 782
    k_gemm_tc<<<GBLK, 512, TC_SMEM>>>(h, b, gamma, beta, out);
}

// round 12
// speedup vs baseline: 1.3938x; 1.0074x over previous
#include <cuda_runtime.h>
#include <cuda_bf16.h>
#include <cstdint>

#define N_NODES 100000
#define N_EDGES 1600000
#define D 128
#define K2 256

#define SCAN_NBLK ((N_NODES + 4095) / 4096)   // 25

// ---------------- scratch (device globals; no allocation allowed) ----------
__device__ int   g_deg[N_NODES];
__device__ int   g_off[N_NODES + 1];
__device__ int   g_cursor[N_NODES];
__device__ int   g_srcs[N_EDGES];
__device__ int   g_blksum[32];
__device__ float g_ahn[(size_t)N_NODES * D];        // aggregated feats
__device__ __nv_bfloat16 g_Whi[128 * 256];          // W bf16 hi
__device__ __nv_bfloat16 g_Wlo[128 * 256];          // W bf16 lo

// ---------------- init: zero degrees + convert W to bf16 hi/lo ---------------
__global__ void k_init(const float* __restrict__ W) {
    int i = blockIdx.x * blockDim.x + threadIdx.x;
    if (i < N_NODES) g_deg[i] = 0;
    if (i < 128 * 256) {
        float v = W[i];
        __nv_bfloat16 hi = __float2bfloat16(v);
        g_Whi[i] = hi;
        g_Wlo[i] = __float2bfloat16(v - __bfloat162float(hi));
    }
}

__global__ void k_count(const int* __restrict__ dst) {
    int e = blockIdx.x * blockDim.x + threadIdx.x;
    if (e < N_EDGES) atomicAdd(&g_deg[dst[e]], 1);
}

// ---- scan pass 1: per-block exclusive scan + block sums ---------------------
__global__ void k_scan1() {
    __shared__ int wsum[32];
    const int b = blockIdx.x, t = threadIdx.x;
    const int lane = t & 31, wid = t >> 5;
    const int base = b * 4096 + t * 4;

    int v0 = 0, v1 = 0, v2 = 0, v3 = 0;
    if (base + 3 < N_NODES) {
        int4 vv = *(const int4*)&g_deg[base];
        v0 = vv.x; v1 = vv.y; v2 = vv.z; v3 = vv.w;
    } else {
        if (base + 0 < N_NODES) v0 = g_deg[base + 0];
        if (base + 1 < N_NODES) v1 = g_deg[base + 1];
        if (base + 2 < N_NODES) v2 = g_deg[base + 2];
        if (base + 3 < N_NODES) v3 = g_deg[base + 3];
    }
    int tsum = v0 + v1 + v2 + v3;

    int x = tsum;
#pragma unroll
    for (int o = 1; o < 32; o <<= 1) {
        int y = __shfl_up_sync(0xffffffffu, x, o);
        if (lane >= o) x += y;
    }
    if (lane == 31) wsum[wid] = x;
    __syncthreads();
    if (wid == 0) {
        int w = wsum[lane];
        int xx = w;
#pragma unroll
        for (int o = 1; o < 32; o <<= 1) {
            int y = __shfl_up_sync(0xffffffffu, xx, o);
            if (lane >= o) xx += y;
        }
        wsum[lane] = xx - w;
        if (lane == 31) g_blksum[b] = xx;
    }
    __syncthreads();

    int prefix = wsum[wid] + (x - tsum);
    if (base + 3 < N_NODES) {
        *(int4*)&g_off[base] = make_int4(prefix, prefix + v0,
                                         prefix + v0 + v1, prefix + v0 + v1 + v2);
    } else {
        if (base + 0 < N_NODES) g_off[base + 0] = prefix;
        if (base + 1 < N_NODES) g_off[base + 1] = prefix + v0;
        if (base + 2 < N_NODES) g_off[base + 2] = prefix + v0 + v1;
        if (base + 3 < N_NODES) g_off[base + 3] = prefix + v0 + v1 + v2;
    }
}

// ---- scan pass 2: every block redundantly scans the 25 block sums, applies --
__global__ void k_scan23() {
    __shared__ int s_off;
    const int b = blockIdx.x, t = threadIdx.x;

    if (t < 32) {
        int v = (t < SCAN_NBLK) ? g_blksum[t] : 0;
        int x = v;
#pragma unroll
        for (int o = 1; o < 32; o <<= 1) {
            int y = __shfl_up_sync(0xffffffffu, x, o);
            if (t >= o) x += y;
        }
        if (t == b) s_off = x - v;     // exclusive offset of this block
    }
    __syncthreads();
    const int off = s_off;

    const int base = b * 4096 + t * 4;
    if (base + 3 < N_NODES) {
        int4 vv = *(const int4*)&g_off[base];
        vv.x += off; vv.y += off; vv.z += off; vv.w += off;
        *(int4*)&g_off[base] = vv;
        *(int4*)&g_cursor[base] = vv;
    } else {
#pragma unroll
        for (int j = 0; j < 4; j++) {
            int idx = base + j;
            if (idx < N_NODES) {
                int val = g_off[idx] + off;
                g_off[idx] = val;
                g_cursor[idx] = val;
            }
        }
    }
    if (b == 0 && t == 0) g_off[N_NODES] = N_EDGES;
}

__global__ void k_scatter(const int* __restrict__ src, const int* __restrict__ dst) {
    int e = blockIdx.x * blockDim.x + threadIdx.x;
    if (e < N_EDGES) {
        int p = atomicAdd(&g_cursor[dst[e]], 1);
        g_srcs[p] = src[e];
    }
}

// ---------------- aggregation: one warp per dst node, 4 gathers in flight ----
__global__ void k_aggregate(const float* __restrict__ h) {
    int warp = (blockIdx.x * blockDim.x + threadIdx.x) >> 5;
    int lane = threadIdx.x & 31;
    if (warp >= N_NODES) return;
    int beg = g_off[warp];
    int end = g_off[warp + 1];
    const float4* h4 = (const float4*)h;
    float4 acc0 = make_float4(0.f, 0.f, 0.f, 0.f);
    float4 acc1 = make_float4(0.f, 0.f, 0.f, 0.f);
    int e = beg;
    for (; e + 3 < end; e += 4) {
        int s0 = __ldg(&g_srcs[e]);
        int s1 = __ldg(&g_srcs[e + 1]);
        int s2 = __ldg(&g_srcs[e + 2]);
        int s3 = __ldg(&g_srcs[e + 3]);
        float4 v0 = __ldg(&h4[(size_t)s0 * 32 + lane]);
        float4 v1 = __ldg(&h4[(size_t)s1 * 32 + lane]);
        float4 v2 = __ldg(&h4[(size_t)s2 * 32 + lane]);
        float4 v3 = __ldg(&h4[(size_t)s3 * 32 + lane]);
        acc0.x += v0.x; acc0.y += v0.y; acc0.z += v0.z; acc0.w += v0.w;
        acc1.x += v1.x; acc1.y += v1.y; acc1.z += v1.z; acc1.w += v1.w;
        acc0.x += v2.x; acc0.y += v2.y; acc0.z += v2.z; acc0.w += v2.w;
        acc1.x += v3.x; acc1.y += v3.y; acc1.z += v3.z; acc1.w += v3.w;
    }
    for (; e < end; e++) {
        int s0 = __ldg(&g_srcs[e]);
        float4 v0 = __ldg(&h4[(size_t)s0 * 32 + lane]);
        acc0.x += v0.x; acc0.y += v0.y; acc0.z += v0.z; acc0.w += v0.w;
    }
    acc0.x += acc1.x; acc0.y += acc1.y; acc0.z += acc1.z; acc0.w += acc1.w;
    float norm = (end > beg) ? 1.0f / (float)(end - beg) : 0.0f;
    acc0.x *= norm; acc0.y *= norm; acc0.z *= norm; acc0.w *= norm;
    ((float4*)g_ahn)[(size_t)warp * 32 + lane] = acc0;
}

// =============== tensor-core GEMM + LN + ReLU (mma.sync bf16 hi/lo) ==========
#define ASTR 72
#define ABYTES (128 * ASTR * 2)
#define BUFBYTES (4 * ABYTES)
#define OFF_WHI 0
#define OFF_WLO (ABYTES)
#define OFF_AHI (2 * ABYTES)
#define OFF_ALO (3 * ABYTES)
#define TC_SMEM (2 * BUFBYTES)
#define OSTR 132

__device__ __forceinline__ uint32_t smem_u32(const void* p) {
    uint32_t a;
    asm("{ .reg .u64 t; cvta.to.shared.u64 t, %1; cvt.u32.u64 %0, t; }"
        : "=r"(a) : "l"(p));
    return a;
}

__device__ __forceinline__ void ldm4(uint32_t* r, uint32_t addr) {
    asm volatile("ldmatrix.sync.aligned.m8n8.x4.shared.b16 {%0,%1,%2,%3}, [%4];"
        : "=r"(r[0]), "=r"(r[1]), "=r"(r[2]), "=r"(r[3]) : "r"(addr));
}

__device__ __forceinline__ void mma_bf16(float* c, const uint32_t* a,
                                         uint32_t b0, uint32_t b1) {
    asm volatile("mma.sync.aligned.m16n8k16.row.col.f32.bf16.bf16.f32 "
        "{%0,%1,%2,%3}, {%4,%5,%6,%7}, {%8,%9}, {%0,%1,%2,%3};"
        : "+f"(c[0]), "+f"(c[1]), "+f"(c[2]), "+f"(c[3])
        : "r"(a[0]), "r"(a[1]), "r"(a[2]), "r"(a[3]), "r"(b0), "r"(b1));
}

__device__ __forceinline__ void split4(float4 v, uint32_t* hi, uint32_t* lo) {
    __nv_bfloat162 ha = __floats2bfloat162_rn(v.x, v.y);
    __nv_bfloat162 hb = __floats2bfloat162_rn(v.z, v.w);
    float2 fa = __bfloat1622float2(ha);
    float2 fb = __bfloat1622float2(hb);
    __nv_bfloat162 la = __floats2bfloat162_rn(v.x - fa.x, v.y - fa.y);
    __nv_bfloat162 lb = __floats2bfloat162_rn(v.z - fb.x, v.w - fb.y);
    hi[0] = *(uint32_t*)&ha; hi[1] = *(uint32_t*)&hb;
    lo[0] = *(uint32_t*)&la; lo[1] = *(uint32_t*)&lb;
}

__global__ void __launch_bounds__(512, 1)
k_gemm_tc(const float* __restrict__ h,
          const float* __restrict__ bias,
          const float* __restrict__ gamma,
          const float* __restrict__ beta,
          float* __restrict__ out)
{
    extern __shared__ char sm[];
    const uint32_t smb = smem_u32(sm);

    const int tid = threadIdx.x;
    const int wid = tid >> 5;
    const int lane = tid & 31;
    const int wm = wid & 3;
    const int wn = wid >> 2;
    const int row0 = blockIdx.x * 128;

    const int sr = tid >> 2;
    const int sq = tid & 3;

    const float4* h4 = (const float4*)h;
    const float4* a4 = (const float4*)g_ahn;

    float c[2][4][4];
#pragma unroll
    for (int i = 0; i < 2; i++)
#pragma unroll
        for (int j = 0; j < 4; j++)
#pragma unroll
            for (int k = 0; k < 4; k++) c[i][j][k] = 0.f;

    const int lrow = lane & 15;
    const int lhalfB = (lane >> 4) * 16;
    const uint32_t aRowB = (uint32_t)(wm * 32 + lrow) * (ASTR * 2);
    const uint32_t wRowB = (uint32_t)(wn * 32 + lrow) * (ASTR * 2);

    int growA = row0 + sr;
    if (growA >= N_NODES) growA = N_NODES - 1;
    const size_t aBase = (size_t)growA * 32;
    const int wIdx = sr * 256 + sq * 16;
    const uint32_t stByteOff = (uint32_t)((sr * ASTR + sq * 16) * 2);

    // ---- stage chunk 0 into buffer 0 ----------------------------------------
    {
        uint32_t hi[8], lo[8];
#pragma unroll
        for (int i = 0; i < 4; i++) {
            float4 v = __ldg(&h4[aBase + sq * 4 + i]);
            split4(v, &hi[2 * i], &lo[2 * i]);
        }
        char* pa = sm + OFF_AHI + stByteOff;
        char* pl = sm + OFF_ALO + stByteOff;
        *(uint4*)pa = make_uint4(hi[0], hi[1], hi[2], hi[3]);
        *(uint4*)(pa + 16) = make_uint4(hi[4], hi[5], hi[6], hi[7]);
        *(uint4*)pl = make_uint4(lo[0], lo[1], lo[2], lo[3]);
        *(uint4*)(pl + 16) = make_uint4(lo[4], lo[5], lo[6], lo[7]);

        uint4 wh0 = __ldg((const uint4*)&g_Whi[wIdx]);
        uint4 wh1 = __ldg((const uint4*)&g_Whi[wIdx + 8]);
        uint4 wl0 = __ldg((const uint4*)&g_Wlo[wIdx]);
        uint4 wl1 = __ldg((const uint4*)&g_Wlo[wIdx + 8]);
        char* pw = sm + OFF_WHI + stByteOff;
        char* pv = sm + OFF_WLO + stByteOff;
        *(uint4*)pw = wh0; *(uint4*)(pw + 16) = wh1;
        *(uint4*)pv = wl0; *(uint4*)(pv + 16) = wl1;
    }
    __syncthreads();

#pragma unroll
    for (int kb = 0; kb < 4; kb++) {
        const bool more = kb < 3;
        float4 preA[4];
        uint4 preW[4];
        if (more) {
            int kn = kb + 1;
            const float4* asrc = (kn < 2) ? h4 : a4;
            int koff = (kn & 1) * 16;
#pragma unroll
            for (int i = 0; i < 4; i++)
                preA[i] = __ldg(&asrc[aBase + koff + sq * 4 + i]);
            preW[0] = __ldg((const uint4*)&g_Whi[wIdx + kn * 64]);
            preW[1] = __ldg((const uint4*)&g_Whi[wIdx + kn * 64 + 8]);
            preW[2] = __ldg((const uint4*)&g_Wlo[wIdx + kn * 64]);
            preW[3] = __ldg((const uint4*)&g_Wlo[wIdx + kn * 64 + 8]);
        }

        const uint32_t bufB = (uint32_t)((kb & 1) * BUFBYTES);
#pragma unroll
        for (int ks = 0; ks < 4; ks++) {
            const uint32_t cb = (uint32_t)(ks * 32 + lhalfB);
            uint32_t ah[2][4], al[2][4], wh[2][4], wl[2][4];
#pragma unroll
            for (int mf = 0; mf < 2; mf++) {
                uint32_t ro = aRowB + mf * 16 * (ASTR * 2) + cb;
                ldm4(ah[mf], smb + bufB + OFF_AHI + ro);
                ldm4(al[mf], smb + bufB + OFF_ALO + ro);
            }
#pragma unroll
            for (int nx = 0; nx < 2; nx++) {
                uint32_t ro = wRowB + nx * 16 * (ASTR * 2) + cb;
                ldm4(wh[nx], smb + bufB + OFF_WHI + ro);
                ldm4(wl[nx], smb + bufB + OFF_WLO + ro);
            }
#pragma unroll
            for (int mf = 0; mf < 2; mf++)
#pragma unroll
                for (int nx = 0; nx < 2; nx++)
#pragma unroll
                    for (int sub = 0; sub < 2; sub++) {
                        int n8 = nx * 2 + sub;
                        mma_bf16(c[mf][n8], ah[mf], wh[nx][sub], wh[nx][sub + 2]);
                        mma_bf16(c[mf][n8], ah[mf], wl[nx][sub], wl[nx][sub + 2]);
                        mma_bf16(c[mf][n8], al[mf], wh[nx][sub], wh[nx][sub + 2]);
                    }
        }

        if (more) {
            const uint32_t nbB = (uint32_t)(((kb + 1) & 1) * BUFBYTES);
            uint32_t hi[8], lo[8];
#pragma unroll
            for (int i = 0; i < 4; i++)
                split4(preA[i], &hi[2 * i], &lo[2 * i]);
            char* pa = sm + nbB + OFF_AHI + stByteOff;
            char* pl = sm + nbB + OFF_ALO + stByteOff;
            *(uint4*)pa = make_uint4(hi[0], hi[1], hi[2], hi[3]);
            *(uint4*)(pa + 16) = make_uint4(hi[4], hi[5], hi[6], hi[7]);
            *(uint4*)pl = make_uint4(lo[0], lo[1], lo[2], lo[3]);
            *(uint4*)(pl + 16) = make_uint4(lo[4], lo[5], lo[6], lo[7]);
            char* pw = sm + nbB + OFF_WHI + stByteOff;
            char* pv = sm + nbB + OFF_WLO + stByteOff;
            *(uint4*)pw = preW[0]; *(uint4*)(pw + 16) = preW[1];
            *(uint4*)pv = preW[2]; *(uint4*)(pv + 16) = preW[3];
            __syncthreads();
        }
    }

    // ---- stage C frags to SMEM ------------------------------------------------
    __syncthreads();
    float* outS = (float*)sm;
#pragma unroll
    for (int mf = 0; mf < 2; mf++)
#pragma unroll
        for (int n8 = 0; n8 < 4; n8++) {
            int rr = wm * 32 + mf * 16 + (lane >> 2);
            int cc = wn * 32 + n8 * 8 + (lane & 3) * 2;
            *(float2*)&outS[rr * OSTR + cc] =
                make_float2(c[mf][n8][0], c[mf][n8][1]);
            *(float2*)&outS[(rr + 8) * OSTR + cc] =
                make_float2(c[mf][n8][2], c[mf][n8][3]);
        }
    __syncthreads();

    // ---- bias + LayerNorm + ReLU; 4 threads per row ----------------------------
    {
        int r = tid >> 2;
        int q = tid & 3;
        float vals[32];
        float s = 0.f, ss = 0.f;
#pragma unroll
        for (int j = 0; j < 8; j++) {
            int col = q * 32 + j * 4;
            float4 y = *(const float4*)&outS[r * OSTR + col];
            float4 bb = __ldg((const float4*)&bias[col]);
            y.x += bb.x; y.y += bb.y; y.z += bb.z; y.w += bb.w;
            vals[4 * j + 0] = y.x; vals[4 * j + 1] = y.y;
            vals[4 * j + 2] = y.z; vals[4 * j + 3] = y.w;
            s += y.x + y.y + y.z + y.w;
            ss += y.x * y.x + y.y * y.y + y.z * y.z + y.w * y.w;
        }
        s  += __shfl_xor_sync(0xffffffffu, s, 1);
        s  += __shfl_xor_sync(0xffffffffu, s, 2);
        ss += __shfl_xor_sync(0xffffffffu, ss, 1);
        ss += __shfl_xor_sync(0xffffffffu, ss, 2);
        float mu = s * (1.0f / 128.0f);
        float var = ss * (1.0f / 128.0f) - mu * mu;
        float inv = rsqrtf(var + 1e-5f);

        int grow = row0 + r;
        if (grow < N_NODES) {
            float* gout = &out[(size_t)grow * 128];
#pragma unroll
            for (int j = 0; j < 8; j++) {
                int col = q * 32 + j * 4;
                float4 gm = __ldg((const float4*)&gamma[col]);
                float4 bt = __ldg((const float4*)&beta[col]);
                float4 o;
                o.x = (vals[4 * j + 0] - mu) * inv * gm.x + bt.x;
                o.y = (vals[4 * j + 1] - mu) * inv * gm.y + bt.y;
                o.z = (vals[4 * j + 2] - mu) * inv * gm.z + bt.z;
                o.w = (vals[4 * j + 3] - mu) * inv * gm.w + bt.w;
                o.x = o.x > 0.f ? o.x : 0.f;
                o.y = o.y > 0.f ? o.y : 0.f;
                o.z = o.z > 0.f ? o.z : 0.f;
                o.w = o.w > 0.f ? o.w : 0.f;
                *(float4*)&gout[col] = o;
            }
        }
    }
}

// ---------------- launcher ---------------------------------------------------
extern "C" void kernel_launch(void* const* d_in, const int* in_sizes, int n_in,
                              void* d_out, int out_size) {
    const float* h     = (const float*)d_in[0];
    const float* W     = (const float*)d_in[1];
    const float* b     = (const float*)d_in[2];
    const float* gamma = (const float*)d_in[3];
    const float* beta  = (const float*)d_in[4];
    const int*   src   = (const int*)d_in[5];
    const int*   dst   = (const int*)d_in[6];
    float* out = (float*)d_out;

    static int inited = 0;
    if (!inited) {
        cudaFuncSetAttribute(k_gemm_tc, cudaFuncAttributeMaxDynamicSharedMemorySize,
                             TC_SMEM);
        inited = 1;
    }

    k_init<<<(N_NODES + 255) / 256, 256>>>(W);                 // launch 1
    k_count<<<(N_EDGES + 255) / 256, 256>>>(dst);              // launch 2
    k_scan1<<<SCAN_NBLK, 1024>>>();                            // launch 3
    k_scan23<<<SCAN_NBLK, 1024>>>();                           // launch 4
    k_scatter<<<(N_EDGES + 255) / 256, 256>>>(src, dst);       // launch 5
    k_aggregate<<<(N_NODES * 32 + 255) / 256, 256>>>(h);       // launch 6 (ncu)
    const int GBLK = (N_NODES + 127) / 128;                    // 782
    k_gemm_tc<<<GBLK, 512, TC_SMEM>>>(h, b, gamma, beta, out); // launch 7
}